// round 15
// baseline (speedup 1.0000x reference)
#include <cuda_runtime.h>
#include <cuda_fp16.h>
#include <cstdint>
#include <math.h>

#define D_MODEL 512
#define SEQ     2048
#define BATCH   8

#define TILE_M  256
#define TILE_N  64
#define CK      32                   // k elems per chunk
#define NIT     (D_MODEL / CK)       // 16 mainloop iterations
#define THREADS 512
#define DT      (D_MODEL / TILE_N)   // 8
#define ST      (SEQ / TILE_M)       // 8
#define GROUPS  64                   // partial rowgroups per (b,d): ST * 8

// smem tiles: rows are 64B (32 halfs)
#define A_TB    (TILE_M * 64)        // 16384
#define B_TB    (TILE_N * 64)        // 4096
// kv stage: A = x1hi, x2hi ; B = wkhi, wklo, wvhi, wvlo
#define KV_STG  (2*A_TB + 4*B_TB)    // 49152
#define KV_SMEM (3 * KV_STG)         // 147456
// q stage: A = x1hi ; B = wqhi, wqlo
#define Q_STG   (A_TB + 2*B_TB)      // 24576
#define Q_SMEM  (3 * Q_STG)          // 73728 (also fits 256xTPITCH transpose)
#define TPITCH  68

// ---------------- device scratch (allocation-free rule) ----------------
#define XELEMS (BATCH * SEQ * D_MODEL)
#define WELEMS (D_MODEL * D_MODEL)
__device__ __half g_x1hi[XELEMS];
__device__ __half g_x2hi[XELEMS];
__device__ __half g_wqhi[WELEMS], g_wqlo[WELEMS];
__device__ __half g_wkhi[WELEMS], g_wklo[WELEMS];
__device__ __half g_wvhi[WELEMS], g_wvlo[WELEMS];
__device__ float g_part1[BATCH * GROUPS * D_MODEL];
__device__ float g_part2[BATCH * GROUPS * D_MODEL];
__device__ float g_ratio[BATCH * D_MODEL];

// ---------------- PTX helpers ----------------
__device__ __forceinline__ uint32_t smem_u32(const void* p) {
    uint32_t a;
    asm("{ .reg .u64 t; cvta.to.shared.u64 t, %1; cvt.u32.u64 %0, t; }" : "=r"(a) : "l"(p));
    return a;
}
__device__ __forceinline__ void cp16(uint32_t dst, const void* src) {
    asm volatile("cp.async.cg.shared.global [%0], [%1], 16;" :: "r"(dst), "l"(src) : "memory");
}
#define CP_COMMIT() asm volatile("cp.async.commit_group;" ::: "memory")
#define CP_WAIT2()  asm volatile("cp.async.wait_group 2;" ::: "memory")

__device__ __forceinline__ void ldsm4(uint32_t* r, uint32_t addr) {
    asm volatile("ldmatrix.sync.aligned.m8n8.x4.shared.b16 {%0,%1,%2,%3}, [%4];"
        : "=r"(r[0]), "=r"(r[1]), "=r"(r[2]), "=r"(r[3]) : "r"(addr));
}
__device__ __forceinline__ void mma16816(float* c, const uint32_t* a, const uint32_t* b) {
    asm volatile("mma.sync.aligned.m16n8k16.row.col.f32.f16.f16.f32 "
        "{%0,%1,%2,%3}, {%4,%5,%6,%7}, {%8,%9}, {%0,%1,%2,%3};"
        : "+f"(c[0]), "+f"(c[1]), "+f"(c[2]), "+f"(c[3])
        : "r"(a[0]), "r"(a[1]), "r"(a[2]), "r"(a[3]), "r"(b[0]), "r"(b[1]));
}

// swizzled byte offset within a tile: row r (64B rows), 16B chunk c8 in 0..3
__device__ __forceinline__ uint32_t soff(int r, int c8) {
    return (uint32_t)(r * 64 + ((c8 ^ ((r >> 1) & 3)) * 16));
}

// ---------------------------------------------------------------------------
// split kernels: fp32 -> fp16 hi (and lo for weights), layout preserved
// ---------------------------------------------------------------------------
__device__ __forceinline__ void split_store(const float4* src, uint2* hi, uint2* lo, int i)
{
    float4 x = src[i];
    __half h0 = __float2half_rn(x.x), h1 = __float2half_rn(x.y);
    __half h2 = __float2half_rn(x.z), h3 = __float2half_rn(x.w);
    __half2 ha = __halves2half2(h0, h1), hb = __halves2half2(h2, h3);
    uint2 uh;
    uh.x = *(uint32_t*)&ha; uh.y = *(uint32_t*)&hb;
    hi[i] = uh;
    if (lo) {
        __half l0 = __float2half_rn(x.x - __half2float(h0));
        __half l1 = __float2half_rn(x.y - __half2float(h1));
        __half l2 = __float2half_rn(x.z - __half2float(h2));
        __half l3 = __float2half_rn(x.w - __half2float(h3));
        __half2 la = __halves2half2(l0, l1), lb = __halves2half2(l2, l3);
        uint2 ul;
        ul.x = *(uint32_t*)&la; ul.y = *(uint32_t*)&lb;
        lo[i] = ul;
    }
}

__global__ void split_x_kernel(const float4* __restrict__ X1, const float4* __restrict__ X2)
{
    int i = blockIdx.x * blockDim.x + threadIdx.x;
    if (i >= XELEMS / 4) return;
    if (blockIdx.z == 0) split_store(X1, (uint2*)g_x1hi, (uint2*)0, i);
    else                 split_store(X2, (uint2*)g_x2hi, (uint2*)0, i);
}

__global__ void split_w_kernel(const float4* __restrict__ Wq,
                               const float4* __restrict__ Wk,
                               const float4* __restrict__ Wv)
{
    int i = blockIdx.x * blockDim.x + threadIdx.x;
    if (i >= WELEMS / 4) return;
    if (blockIdx.z == 0)      split_store(Wq, (uint2*)g_wqhi, (uint2*)g_wqlo, i);
    else if (blockIdx.z == 1) split_store(Wk, (uint2*)g_wkhi, (uint2*)g_wklo, i);
    else                      split_store(Wv, (uint2*)g_wvhi, (uint2*)g_wvlo, i);
}

// ---------------------------------------------------------------------------
// kv kernel (M=256, 16 warps): k = X1@Wk^T, v = X2@Wv^T (2-term each),
// fused epilogue: partials of sum_s ws*e^(k+bk)*(v+bv) and sum_s ws*e^(k+bk)
// ---------------------------------------------------------------------------
__global__ __launch_bounds__(THREADS) void kv_kernel(
    const float* __restrict__ bk, const float* __restrict__ bv,
    const float* __restrict__ PB)
{
    extern __shared__ __align__(128) char smem[];
    const uint32_t sb = smem_u32(smem);
    const int tid = threadIdx.x, wid = tid >> 5, L = tid & 31;
    const int wm = wid & 7, wn = wid >> 3;

    const int dt = blockIdx.x, st = blockIdx.y, b = blockIdx.z;
    const int s0 = st * TILE_M, d0 = dt * TILE_N;

    // ---- per-thread cp.async offsets (chunk-invariant) ----
    int asrc[2]; uint32_t adst[2];
#pragma unroll
    for (int p = 0; p < 2; p++) {
        int idx = tid + p * THREADS;
        int r = idx >> 2, c8 = idx & 3;
        asrc[p] = r * D_MODEL + c8 * 8; adst[p] = soff(r, c8);
    }
    const int brow = (tid & 255) >> 2, bc8 = tid & 3;
    const int bsrc = brow * D_MODEL + bc8 * 8;
    const uint32_t bdst = soff(brow, bc8);
    const bool bldr = (tid < 256);

    // ---- ldmatrix addresses (chunk-invariant, per lane) ----
    uint32_t offA[2][2], offB[2][2];
#pragma unroll
    for (int i = 0; i < 2; i++)
#pragma unroll
        for (int ks = 0; ks < 2; ks++) {
            int r = wm * 32 + i * 16 + (L & 7) + ((L >> 3) & 1) * 8;
            int c8 = ks * 2 + (L >> 4);
            offA[i][ks] = soff(r, c8);
        }
#pragma unroll
    for (int jp = 0; jp < 2; jp++)
#pragma unroll
        for (int ks = 0; ks < 2; ks++) {
            int n = wn * 32 + (jp * 2 + (L >> 4)) * 8 + (L & 7);
            int c8 = ks * 2 + ((L >> 3) & 1);
            offB[jp][ks] = soff(n, c8);
        }

    const size_t xbase = ((size_t)b * SEQ + s0) * D_MODEL;
    const __half* x1h = g_x1hi + xbase;
    const __half* x2h = g_x2hi + xbase;
    const size_t wbase = (size_t)d0 * D_MODEL;
    const __half* wkh = g_wkhi + wbase;
    const __half* wkl = g_wklo + wbase;
    const __half* wvh = g_wvhi + wbase;
    const __half* wvl = g_wvlo + wbase;

    float accK[2][4][4], accV[2][4][4];
#pragma unroll
    for (int i = 0; i < 2; i++)
#pragma unroll
        for (int j = 0; j < 4; j++)
#pragma unroll
            for (int e = 0; e < 4; e++) { accK[i][j][e] = 0.f; accV[i][j][e] = 0.f; }

#define KV_ISSUE(cc) do { \
        int _k0 = (cc) * CK; \
        uint32_t _S = sb + ((cc) % 3) * KV_STG; \
        cp16(_S + 0*A_TB + adst[0], x1h + asrc[0] + _k0); \
        cp16(_S + 0*A_TB + adst[1], x1h + asrc[1] + _k0); \
        cp16(_S + 1*A_TB + adst[0], x2h + asrc[0] + _k0); \
        cp16(_S + 1*A_TB + adst[1], x2h + asrc[1] + _k0); \
        if (bldr) { \
            cp16(_S + 2*A_TB + 0*B_TB + bdst, wkh + bsrc + _k0); \
            cp16(_S + 2*A_TB + 1*B_TB + bdst, wkl + bsrc + _k0); \
            cp16(_S + 2*A_TB + 2*B_TB + bdst, wvh + bsrc + _k0); \
            cp16(_S + 2*A_TB + 3*B_TB + bdst, wvl + bsrc + _k0); \
        } \
        CP_COMMIT(); \
    } while (0)

    KV_ISSUE(0); KV_ISSUE(1); KV_ISSUE(2);

    for (int c = 0; c < NIT; c++) {
        CP_WAIT2();
        __syncthreads();
        const uint32_t sA1h = sb + (c % 3) * KV_STG;
        const uint32_t sA2h = sA1h + A_TB;
        const uint32_t sBB  = sA1h + 2 * A_TB;
#pragma unroll
        for (int ks = 0; ks < 2; ks++) {
            // ---- K gemm (2-term): accK += A1hi*Bkhi + A1hi*Bklo ----
            {
                uint32_t ah[2][4], bh[2][4], bl[2][4];
                ldsm4(ah[0], sA1h + offA[0][ks]);
                ldsm4(ah[1], sA1h + offA[1][ks]);
                ldsm4(bh[0], sBB + 0*B_TB + offB[0][ks]);
                ldsm4(bh[1], sBB + 0*B_TB + offB[1][ks]);
                ldsm4(bl[0], sBB + 1*B_TB + offB[0][ks]);
                ldsm4(bl[1], sBB + 1*B_TB + offB[1][ks]);
#pragma unroll
                for (int i = 0; i < 2; i++)
#pragma unroll
                    for (int j = 0; j < 4; j++) {
                        mma16816(accK[i][j], ah[i], &bh[j >> 1][(j & 1) * 2]);
                        mma16816(accK[i][j], ah[i], &bl[j >> 1][(j & 1) * 2]);
                    }
            }
            // ---- V gemm (2-term): accV += A2hi*Bvhi + A2hi*Bvlo ----
            {
                uint32_t ah[2][4], bh[2][4], bl[2][4];
                ldsm4(ah[0], sA2h + offA[0][ks]);
                ldsm4(ah[1], sA2h + offA[1][ks]);
                ldsm4(bh[0], sBB + 2*B_TB + offB[0][ks]);
                ldsm4(bh[1], sBB + 2*B_TB + offB[1][ks]);
                ldsm4(bl[0], sBB + 3*B_TB + offB[0][ks]);
                ldsm4(bl[1], sBB + 3*B_TB + offB[1][ks]);
#pragma unroll
                for (int i = 0; i < 2; i++)
#pragma unroll
                    for (int j = 0; j < 4; j++) {
                        mma16816(accV[i][j], ah[i], &bh[j >> 1][(j & 1) * 2]);
                        mma16816(accV[i][j], ah[i], &bl[j >> 1][(j & 1) * 2]);
                    }
            }
        }
        __syncthreads();
        if (c + 3 < NIT) KV_ISSUE(c + 3);
    }
#undef KV_ISSUE

    // ---- epilogue (same math as R14; wm now 0..7, 8 rowgroups) ----
    float ws[2][2];
#pragma unroll
    for (int i = 0; i < 2; i++)
#pragma unroll
        for (int h = 0; h < 2; h++)
            ws[i][h] = __expf(PB[s0 + wm * 32 + i * 16 + (L >> 2) + h * 8]);

    const int colb = d0 + wn * 32 + (L & 3) * 2;
    float2 bk2[4], bv2[4];
#pragma unroll
    for (int j = 0; j < 4; j++) {
        bk2[j] = *(const float2*)(bk + colb + j * 8);
        bv2[j] = *(const float2*)(bv + colb + j * 8);
    }
    float p1[8], p2[8];
#pragma unroll
    for (int u = 0; u < 8; u++) { p1[u] = 0.f; p2[u] = 0.f; }
#pragma unroll
    for (int i = 0; i < 2; i++)
#pragma unroll
        for (int h = 0; h < 2; h++)
#pragma unroll
            for (int j = 0; j < 4; j++) {
                float ek0 = ws[i][h] * __expf(accK[i][j][h * 2 + 0] + bk2[j].x);
                float ek1 = ws[i][h] * __expf(accK[i][j][h * 2 + 1] + bk2[j].y);
                p2[j * 2 + 0] += ek0;
                p2[j * 2 + 1] += ek1;
                p1[j * 2 + 0] += ek0 * (accV[i][j][h * 2 + 0] + bv2[j].x);
                p1[j * 2 + 1] += ek1 * (accV[i][j][h * 2 + 1] + bv2[j].y);
            }
#pragma unroll
    for (int sft = 4; sft <= 16; sft <<= 1)
#pragma unroll
        for (int u = 0; u < 8; u++) {
            p1[u] += __shfl_xor_sync(0xffffffffu, p1[u], sft);
            p2[u] += __shfl_xor_sync(0xffffffffu, p2[u], sft);
        }
    if ((L >> 2) == 0) {
        size_t pb = (((size_t)b * ST + st) * 8 + wm) * D_MODEL + colb;
#pragma unroll
        for (int j = 0; j < 4; j++) {
            *(float2*)(g_part1 + pb + j * 8) = make_float2(p1[j * 2], p1[j * 2 + 1]);
            *(float2*)(g_part2 + pb + j * 8) = make_float2(p2[j * 2], p2[j * 2 + 1]);
        }
    }
}

// ---------------------------------------------------------------------------
// ratio kernel: 4 lanes per (b,d), shfl merge — deterministic, higher MLP
// ---------------------------------------------------------------------------
__global__ void ratio_kernel()
{
    int t = blockIdx.x * blockDim.x + threadIdx.x;
    if (t >= BATCH * D_MODEL * 4) return;
    int pair = t >> 2, sub = t & 3;
    int b = pair >> 9, d = pair & 511;
    float s1 = 0.f, s2 = 0.f;
    int i0 = sub * 16;
#pragma unroll 16
    for (int i = i0; i < i0 + 16; i++) {
        size_t o = ((size_t)b * GROUPS + i) * D_MODEL + d;
        s1 += g_part1[o];
        s2 += g_part2[o];
    }
    s1 += __shfl_xor_sync(0xffffffffu, s1, 1);
    s2 += __shfl_xor_sync(0xffffffffu, s2, 1);
    s1 += __shfl_xor_sync(0xffffffffu, s1, 2);
    s2 += __shfl_xor_sync(0xffffffffu, s2, 2);
    if (sub == 0) g_ratio[pair] = s1 / s2;
}

// ---------------------------------------------------------------------------
// q kernel (M=256, 16 warps): q = X1@Wq^T + bq (2-term),
// out = sigmoid(q) * ratio[b,d]
// ---------------------------------------------------------------------------
__global__ __launch_bounds__(THREADS) void q_kernel(
    const float* __restrict__ bq, float* __restrict__ out)
{
    extern __shared__ __align__(128) char smem[];
    const uint32_t sb = smem_u32(smem);
    const int tid = threadIdx.x, wid = tid >> 5, L = tid & 31;
    const int wm = wid & 7, wn = wid >> 3;

    const int dt = blockIdx.x, st = blockIdx.y, b = blockIdx.z;
    const int s0 = st * TILE_M, d0 = dt * TILE_N;

    int asrc[2]; uint32_t adst[2];
#pragma unroll
    for (int p = 0; p < 2; p++) {
        int idx = tid + p * THREADS;
        int r = idx >> 2, c8 = idx & 3;
        asrc[p] = r * D_MODEL + c8 * 8; adst[p] = soff(r, c8);
    }
    const int brow = (tid & 255) >> 2, bc8 = tid & 3;
    const int bsrc = brow * D_MODEL + bc8 * 8;
    const uint32_t bdst = soff(brow, bc8);
    const bool bldr = (tid < 256);

    uint32_t offA[2][2], offB[2][2];
#pragma unroll
    for (int i = 0; i < 2; i++)
#pragma unroll
        for (int ks = 0; ks < 2; ks++) {
            int r = wm * 32 + i * 16 + (L & 7) + ((L >> 3) & 1) * 8;
            int c8 = ks * 2 + (L >> 4);
            offA[i][ks] = soff(r, c8);
        }
#pragma unroll
    for (int jp = 0; jp < 2; jp++)
#pragma unroll
        for (int ks = 0; ks < 2; ks++) {
            int n = wn * 32 + (jp * 2 + (L >> 4)) * 8 + (L & 7);
            int c8 = ks * 2 + ((L >> 3) & 1);
            offB[jp][ks] = soff(n, c8);
        }

    const size_t xbase = ((size_t)b * SEQ + s0) * D_MODEL;
    const __half* xh = g_x1hi + xbase;
    const size_t wbase = (size_t)d0 * D_MODEL;
    const __half* wh = g_wqhi + wbase;
    const __half* wl = g_wqlo + wbase;

    float acc[2][4][4];
#pragma unroll
    for (int i = 0; i < 2; i++)
#pragma unroll
        for (int j = 0; j < 4; j++)
#pragma unroll
            for (int e = 0; e < 4; e++) acc[i][j][e] = 0.f;

#define Q_ISSUE(cc) do { \
        int _k0 = (cc) * CK; \
        uint32_t _S = sb + ((cc) % 3) * Q_STG; \
        cp16(_S + 0*A_TB + adst[0], xh + asrc[0] + _k0); \
        cp16(_S + 0*A_TB + adst[1], xh + asrc[1] + _k0); \
        if (bldr) { \
            cp16(_S + A_TB + 0*B_TB + bdst, wh + bsrc + _k0); \
            cp16(_S + A_TB + 1*B_TB + bdst, wl + bsrc + _k0); \
        } \
        CP_COMMIT(); \
    } while (0)

    Q_ISSUE(0); Q_ISSUE(1); Q_ISSUE(2);

    for (int c = 0; c < NIT; c++) {
        CP_WAIT2();
        __syncthreads();
        const uint32_t sAh = sb + (c % 3) * Q_STG;
        const uint32_t sBh = sAh + A_TB;
        const uint32_t sBl = sBh + B_TB;
#pragma unroll
        for (int ks = 0; ks < 2; ks++) {
            uint32_t ah[2][4], bh[2][4], bl[2][4];
            ldsm4(ah[0], sAh + offA[0][ks]);
            ldsm4(ah[1], sAh + offA[1][ks]);
            ldsm4(bh[0], sBh + offB[0][ks]);
            ldsm4(bh[1], sBh + offB[1][ks]);
            ldsm4(bl[0], sBl + offB[0][ks]);
            ldsm4(bl[1], sBl + offB[1][ks]);
#pragma unroll
            for (int i = 0; i < 2; i++)
#pragma unroll
                for (int j = 0; j < 4; j++) {
                    mma16816(acc[i][j], ah[i], &bh[j >> 1][(j & 1) * 2]);
                    mma16816(acc[i][j], ah[i], &bl[j >> 1][(j & 1) * 2]);
                }
        }
        __syncthreads();
        if (c + 3 < NIT) Q_ISSUE(c + 3);
    }
#undef Q_ISSUE

    // ---- epilogue: sigmoid * ratio via smem transpose for coalesced out ----
    const int colb = wn * 32 + (L & 3) * 2;
    float2 bq2[4], rt2[4];
#pragma unroll
    for (int j = 0; j < 4; j++) {
        bq2[j] = *(const float2*)(bq + d0 + colb + j * 8);
        rt2[j] = *(const float2*)(g_ratio + (size_t)b * D_MODEL + d0 + colb + j * 8);
    }
    float* tb = (float*)smem;
#pragma unroll
    for (int i = 0; i < 2; i++)
#pragma unroll
        for (int h = 0; h < 2; h++) {
            int row = wm * 32 + i * 16 + (L >> 2) + h * 8;
#pragma unroll
            for (int j = 0; j < 4; j++) {
                float q0 = acc[i][j][h * 2 + 0] + bq2[j].x;
                float q1 = acc[i][j][h * 2 + 1] + bq2[j].y;
                float v0 = rt2[j].x / (1.f + __expf(-q0));
                float v1 = rt2[j].y / (1.f + __expf(-q1));
                tb[row * TPITCH + colb + j * 8 + 0] = v0;
                tb[row * TPITCH + colb + j * 8 + 1] = v1;
            }
        }
    __syncthreads();
    float* outp = out + ((size_t)b * SEQ + s0) * D_MODEL + d0;
#pragma unroll
    for (int i = 0; i < 8; i++) {
        int idx = tid + i * THREADS;
        int r = idx >> 4, c4 = idx & 15;
        float4 v = *(float4*)(tb + r * TPITCH + c4 * 4);
        *(float4*)(outp + (size_t)r * D_MODEL + c4 * 4) = v;
    }
}

// ---------------------------------------------------------------------------
extern "C" void kernel_launch(void* const* d_in, const int* in_sizes, int n_in,
                              void* d_out, int out_size)
{
    const float* X1 = (const float*)d_in[0];
    const float* X2 = (const float*)d_in[1];
    const float* Wq = (const float*)d_in[2];
    const float* bq = (const float*)d_in[3];
    const float* Wk = (const float*)d_in[4];
    const float* bk = (const float*)d_in[5];
    const float* Wv = (const float*)d_in[6];
    const float* bv = (const float*)d_in[7];
    const float* PB = (const float*)d_in[8];
    float* out = (float*)d_out;

    cudaFuncSetAttribute(kv_kernel, cudaFuncAttributeMaxDynamicSharedMemorySize, KV_SMEM);
    cudaFuncSetAttribute(q_kernel,  cudaFuncAttributeMaxDynamicSharedMemorySize, Q_SMEM);

    const int xn4 = XELEMS / 4, wn4 = WELEMS / 4;
    dim3 gx((xn4 + 255) / 256, 1, 2);
    dim3 gw((wn4 + 255) / 256, 1, 3);
    split_x_kernel<<<gx, 256>>>((const float4*)X1, (const float4*)X2);
    split_w_kernel<<<gw, 256>>>((const float4*)Wq, (const float4*)Wk, (const float4*)Wv);

    dim3 grid(DT, ST, BATCH);
    kv_kernel<<<grid, THREADS, KV_SMEM>>>(bk, bv, PB);
    ratio_kernel<<<(BATCH * D_MODEL * 4 + 255) / 256, 256>>>();
    q_kernel<<<grid, THREADS, Q_SMEM>>>(bq, out);
}

// round 16
// speedup vs baseline: 1.2123x; 1.2123x over previous
#include <cuda_runtime.h>
#include <cuda_fp16.h>
#include <cstdint>
#include <math.h>

#define D_MODEL 512
#define SEQ     2048
#define BATCH   8

#define TILE_M  128
#define TILE_N  64
#define CK      32                   // k elems per chunk
#define NIT     (D_MODEL / CK)       // 16 mainloop iterations
#define THREADS 256
#define DT      (D_MODEL / TILE_N)   // 8
#define ST      (SEQ / TILE_M)       // 16
#define GROUPS  (ST * 4)             // 64 partial rowgroups per (b,d)

// smem tiles: rows are 64B (32 halfs)
#define A_TB    (TILE_M * 64)        // 8192
#define B_TB    (TILE_N * 64)        // 4096
// kv stage: A = x1hi, x2hi ; B = wkhi, wklo, wvhi, wvlo
#define KV_STG  (2*A_TB + 4*B_TB)    // 32768
#define KV_SMEM (3 * KV_STG)         // 98304 -> 2 CTA/SM
// q stage: A = x1hi ; B = wqhi, wqlo ; + inline-ratio scratch
#define Q_STG   (A_TB + 2*B_TB)      // 16384
#define Q_RP    (3 * Q_STG)          // rp[2][4][64] floats @ 49152
#define Q_RS    (Q_RP + 2048)        // ratio_s[64] floats  @ 51200
#define Q_SMEM  (Q_RS + 256)         // 51456 -> 2 CTA/SM
#define TPITCH  68

// ---------------- device scratch (allocation-free rule) ----------------
#define XELEMS (BATCH * SEQ * D_MODEL)
#define WELEMS (D_MODEL * D_MODEL)
__device__ __half g_x1hi[XELEMS];
__device__ __half g_x2hi[XELEMS];
__device__ __half g_wqhi[WELEMS], g_wqlo[WELEMS];
__device__ __half g_wkhi[WELEMS], g_wklo[WELEMS];
__device__ __half g_wvhi[WELEMS], g_wvlo[WELEMS];
__device__ float g_part1[BATCH * GROUPS * D_MODEL];
__device__ float g_part2[BATCH * GROUPS * D_MODEL];

// ---------------- PTX helpers ----------------
__device__ __forceinline__ uint32_t smem_u32(const void* p) {
    uint32_t a;
    asm("{ .reg .u64 t; cvta.to.shared.u64 t, %1; cvt.u32.u64 %0, t; }" : "=r"(a) : "l"(p));
    return a;
}
__device__ __forceinline__ void cp16(uint32_t dst, const void* src) {
    asm volatile("cp.async.cg.shared.global [%0], [%1], 16;" :: "r"(dst), "l"(src) : "memory");
}
#define CP_COMMIT() asm volatile("cp.async.commit_group;" ::: "memory")
#define CP_WAIT2()  asm volatile("cp.async.wait_group 2;" ::: "memory")

__device__ __forceinline__ void ldsm4(uint32_t* r, uint32_t addr) {
    asm volatile("ldmatrix.sync.aligned.m8n8.x4.shared.b16 {%0,%1,%2,%3}, [%4];"
        : "=r"(r[0]), "=r"(r[1]), "=r"(r[2]), "=r"(r[3]) : "r"(addr));
}
__device__ __forceinline__ void mma16816(float* c, const uint32_t* a, const uint32_t* b) {
    asm volatile("mma.sync.aligned.m16n8k16.row.col.f32.f16.f16.f32 "
        "{%0,%1,%2,%3}, {%4,%5,%6,%7}, {%8,%9}, {%0,%1,%2,%3};"
        : "+f"(c[0]), "+f"(c[1]), "+f"(c[2]), "+f"(c[3])
        : "r"(a[0]), "r"(a[1]), "r"(a[2]), "r"(a[3]), "r"(b[0]), "r"(b[1]));
}

// swizzled byte offset within a tile: row r (64B rows), 16B chunk c8 in 0..3
__device__ __forceinline__ uint32_t soff(int r, int c8) {
    return (uint32_t)(r * 64 + ((c8 ^ ((r >> 1) & 3)) * 16));
}

// ---------------------------------------------------------------------------
// split kernels: fp32 -> fp16 hi (and lo for weights), layout preserved
// ---------------------------------------------------------------------------
__device__ __forceinline__ void split_store(const float4* src, uint2* hi, uint2* lo, int i)
{
    float4 x = src[i];
    __half h0 = __float2half_rn(x.x), h1 = __float2half_rn(x.y);
    __half h2 = __float2half_rn(x.z), h3 = __float2half_rn(x.w);
    __half2 ha = __halves2half2(h0, h1), hb = __halves2half2(h2, h3);
    uint2 uh;
    uh.x = *(uint32_t*)&ha; uh.y = *(uint32_t*)&hb;
    hi[i] = uh;
    if (lo) {
        __half l0 = __float2half_rn(x.x - __half2float(h0));
        __half l1 = __float2half_rn(x.y - __half2float(h1));
        __half l2 = __float2half_rn(x.z - __half2float(h2));
        __half l3 = __float2half_rn(x.w - __half2float(h3));
        __half2 la = __halves2half2(l0, l1), lb = __halves2half2(l2, l3);
        uint2 ul;
        ul.x = *(uint32_t*)&la; ul.y = *(uint32_t*)&lb;
        lo[i] = ul;
    }
}

__global__ void split_x_kernel(const float4* __restrict__ X1, const float4* __restrict__ X2)
{
    int i = blockIdx.x * blockDim.x + threadIdx.x;
    if (i >= XELEMS / 4) return;
    if (blockIdx.z == 0) split_store(X1, (uint2*)g_x1hi, (uint2*)0, i);
    else                 split_store(X2, (uint2*)g_x2hi, (uint2*)0, i);
}

__global__ void split_w_kernel(const float4* __restrict__ Wq,
                               const float4* __restrict__ Wk,
                               const float4* __restrict__ Wv)
{
    int i = blockIdx.x * blockDim.x + threadIdx.x;
    if (i >= WELEMS / 4) return;
    if (blockIdx.z == 0)      split_store(Wq, (uint2*)g_wqhi, (uint2*)g_wqlo, i);
    else if (blockIdx.z == 1) split_store(Wk, (uint2*)g_wkhi, (uint2*)g_wklo, i);
    else                      split_store(Wv, (uint2*)g_wvhi, (uint2*)g_wvlo, i);
}

// ---------------------------------------------------------------------------
// kv kernel (R14, verified): k = X1@Wk^T, v = X2@Wv^T (2-term each),
// fused epilogue: partials of sum_s ws*e^(k+bk)*(v+bv) and sum_s ws*e^(k+bk)
// ---------------------------------------------------------------------------
__global__ __launch_bounds__(THREADS, 2) void kv_kernel(
    const float* __restrict__ bk, const float* __restrict__ bv,
    const float* __restrict__ PB)
{
    extern __shared__ __align__(128) char smem[];
    const uint32_t sb = smem_u32(smem);
    const int tid = threadIdx.x, wid = tid >> 5, L = tid & 31;
    const int wm = wid & 3, wn = wid >> 2;

    const int dt = blockIdx.x, st = blockIdx.y, b = blockIdx.z;
    const int s0 = st * TILE_M, d0 = dt * TILE_N;

    int asrc[2]; uint32_t adst[2];
#pragma unroll
    for (int p = 0; p < 2; p++) {
        int idx = tid + p * THREADS;
        int r = idx >> 2, c8 = idx & 3;
        asrc[p] = r * D_MODEL + c8 * 8; adst[p] = soff(r, c8);
    }
    const int brow = tid >> 2, bc8 = tid & 3;
    const int bsrc = brow * D_MODEL + bc8 * 8;
    const uint32_t bdst = soff(brow, bc8);

    uint32_t offA[2][2], offB[2][2];
#pragma unroll
    for (int i = 0; i < 2; i++)
#pragma unroll
        for (int ks = 0; ks < 2; ks++) {
            int r = wm * 32 + i * 16 + (L & 7) + ((L >> 3) & 1) * 8;
            int c8 = ks * 2 + (L >> 4);
            offA[i][ks] = soff(r, c8);
        }
#pragma unroll
    for (int jp = 0; jp < 2; jp++)
#pragma unroll
        for (int ks = 0; ks < 2; ks++) {
            int n = wn * 32 + (jp * 2 + (L >> 4)) * 8 + (L & 7);
            int c8 = ks * 2 + ((L >> 3) & 1);
            offB[jp][ks] = soff(n, c8);
        }

    const size_t xbase = ((size_t)b * SEQ + s0) * D_MODEL;
    const __half* x1h = g_x1hi + xbase;
    const __half* x2h = g_x2hi + xbase;
    const size_t wbase = (size_t)d0 * D_MODEL;
    const __half* wkh = g_wkhi + wbase;
    const __half* wkl = g_wklo + wbase;
    const __half* wvh = g_wvhi + wbase;
    const __half* wvl = g_wvlo + wbase;

    float accK[2][4][4], accV[2][4][4];
#pragma unroll
    for (int i = 0; i < 2; i++)
#pragma unroll
        for (int j = 0; j < 4; j++)
#pragma unroll
            for (int e = 0; e < 4; e++) { accK[i][j][e] = 0.f; accV[i][j][e] = 0.f; }

#define KV_ISSUE(cc) do { \
        int _k0 = (cc) * CK; \
        uint32_t _S = sb + ((cc) % 3) * KV_STG; \
        cp16(_S + 0*A_TB + adst[0], x1h + asrc[0] + _k0); \
        cp16(_S + 0*A_TB + adst[1], x1h + asrc[1] + _k0); \
        cp16(_S + 1*A_TB + adst[0], x2h + asrc[0] + _k0); \
        cp16(_S + 1*A_TB + adst[1], x2h + asrc[1] + _k0); \
        cp16(_S + 2*A_TB + 0*B_TB + bdst, wkh + bsrc + _k0); \
        cp16(_S + 2*A_TB + 1*B_TB + bdst, wkl + bsrc + _k0); \
        cp16(_S + 2*A_TB + 2*B_TB + bdst, wvh + bsrc + _k0); \
        cp16(_S + 2*A_TB + 3*B_TB + bdst, wvl + bsrc + _k0); \
        CP_COMMIT(); \
    } while (0)

    KV_ISSUE(0); KV_ISSUE(1); KV_ISSUE(2);

    for (int c = 0; c < NIT; c++) {
        CP_WAIT2();
        __syncthreads();
        const uint32_t sA1h = sb + (c % 3) * KV_STG;
        const uint32_t sA2h = sA1h + A_TB;
        const uint32_t sBB  = sA1h + 2 * A_TB;
#pragma unroll
        for (int ks = 0; ks < 2; ks++) {
            {
                uint32_t ah[2][4], bh[2][4], bl[2][4];
                ldsm4(ah[0], sA1h + offA[0][ks]);
                ldsm4(ah[1], sA1h + offA[1][ks]);
                ldsm4(bh[0], sBB + 0*B_TB + offB[0][ks]);
                ldsm4(bh[1], sBB + 0*B_TB + offB[1][ks]);
                ldsm4(bl[0], sBB + 1*B_TB + offB[0][ks]);
                ldsm4(bl[1], sBB + 1*B_TB + offB[1][ks]);
#pragma unroll
                for (int i = 0; i < 2; i++)
#pragma unroll
                    for (int j = 0; j < 4; j++) {
                        mma16816(accK[i][j], ah[i], &bh[j >> 1][(j & 1) * 2]);
                        mma16816(accK[i][j], ah[i], &bl[j >> 1][(j & 1) * 2]);
                    }
            }
            {
                uint32_t ah[2][4], bh[2][4], bl[2][4];
                ldsm4(ah[0], sA2h + offA[0][ks]);
                ldsm4(ah[1], sA2h + offA[1][ks]);
                ldsm4(bh[0], sBB + 2*B_TB + offB[0][ks]);
                ldsm4(bh[1], sBB + 2*B_TB + offB[1][ks]);
                ldsm4(bl[0], sBB + 3*B_TB + offB[0][ks]);
                ldsm4(bl[1], sBB + 3*B_TB + offB[1][ks]);
#pragma unroll
                for (int i = 0; i < 2; i++)
#pragma unroll
                    for (int j = 0; j < 4; j++) {
                        mma16816(accV[i][j], ah[i], &bh[j >> 1][(j & 1) * 2]);
                        mma16816(accV[i][j], ah[i], &bl[j >> 1][(j & 1) * 2]);
                    }
            }
        }
        __syncthreads();
        if (c + 3 < NIT) KV_ISSUE(c + 3);
    }
#undef KV_ISSUE

    float ws[2][2];
#pragma unroll
    for (int i = 0; i < 2; i++)
#pragma unroll
        for (int h = 0; h < 2; h++)
            ws[i][h] = __expf(PB[s0 + wm * 32 + i * 16 + (L >> 2) + h * 8]);

    const int colb = d0 + wn * 32 + (L & 3) * 2;
    float2 bk2[4], bv2[4];
#pragma unroll
    for (int j = 0; j < 4; j++) {
        bk2[j] = *(const float2*)(bk + colb + j * 8);
        bv2[j] = *(const float2*)(bv + colb + j * 8);
    }
    float p1[8], p2[8];
#pragma unroll
    for (int u = 0; u < 8; u++) { p1[u] = 0.f; p2[u] = 0.f; }
#pragma unroll
    for (int i = 0; i < 2; i++)
#pragma unroll
        for (int h = 0; h < 2; h++)
#pragma unroll
            for (int j = 0; j < 4; j++) {
                float ek0 = ws[i][h] * __expf(accK[i][j][h * 2 + 0] + bk2[j].x);
                float ek1 = ws[i][h] * __expf(accK[i][j][h * 2 + 1] + bk2[j].y);
                p2[j * 2 + 0] += ek0;
                p2[j * 2 + 1] += ek1;
                p1[j * 2 + 0] += ek0 * (accV[i][j][h * 2 + 0] + bv2[j].x);
                p1[j * 2 + 1] += ek1 * (accV[i][j][h * 2 + 1] + bv2[j].y);
            }
#pragma unroll
    for (int sft = 4; sft <= 16; sft <<= 1)
#pragma unroll
        for (int u = 0; u < 8; u++) {
            p1[u] += __shfl_xor_sync(0xffffffffu, p1[u], sft);
            p2[u] += __shfl_xor_sync(0xffffffffu, p2[u], sft);
        }
    if ((L >> 2) == 0) {
        size_t pb = (((size_t)b * ST + st) * 4 + wm) * D_MODEL + colb;
#pragma unroll
        for (int j = 0; j < 4; j++) {
            *(float2*)(g_part1 + pb + j * 8) = make_float2(p1[j * 2], p1[j * 2 + 1]);
            *(float2*)(g_part2 + pb + j * 8) = make_float2(p2[j * 2], p2[j * 2 + 1]);
        }
    }
}

// ---------------------------------------------------------------------------
// q kernel: inline ratio reduction (overlapped with pipeline fill) +
// q = X1@Wq^T + bq (2-term), out = sigmoid(q) * ratio
// ---------------------------------------------------------------------------
__global__ __launch_bounds__(THREADS, 2) void q_kernel(
    const float* __restrict__ bq, float* __restrict__ out)
{
    extern __shared__ __align__(128) char smem[];
    const uint32_t sb = smem_u32(smem);
    const int tid = threadIdx.x, wid = tid >> 5, L = tid & 31;
    const int wm = wid & 3, wn = wid >> 2;

    const int dt = blockIdx.x, st = blockIdx.y, b = blockIdx.z;
    const int s0 = st * TILE_M, d0 = dt * TILE_N;

    int asrc[2]; uint32_t adst[2];
#pragma unroll
    for (int p = 0; p < 2; p++) {
        int idx = tid + p * THREADS;
        int r = idx >> 2, c8 = idx & 3;
        asrc[p] = r * D_MODEL + c8 * 8; adst[p] = soff(r, c8);
    }
    const int brow = tid >> 2, bc8 = tid & 3;
    const int bsrc = brow * D_MODEL + bc8 * 8;
    const uint32_t bdst = soff(brow, bc8);

    uint32_t offA[2][2], offB[2][2];
#pragma unroll
    for (int i = 0; i < 2; i++)
#pragma unroll
        for (int ks = 0; ks < 2; ks++) {
            int r = wm * 32 + i * 16 + (L & 7) + ((L >> 3) & 1) * 8;
            int c8 = ks * 2 + (L >> 4);
            offA[i][ks] = soff(r, c8);
        }
#pragma unroll
    for (int jp = 0; jp < 2; jp++)
#pragma unroll
        for (int ks = 0; ks < 2; ks++) {
            int n = wn * 32 + (jp * 2 + (L >> 4)) * 8 + (L & 7);
            int c8 = ks * 2 + ((L >> 3) & 1);
            offB[jp][ks] = soff(n, c8);
        }

    const size_t xbase = ((size_t)b * SEQ + s0) * D_MODEL;
    const __half* xh = g_x1hi + xbase;
    const size_t wbase = (size_t)d0 * D_MODEL;
    const __half* wh = g_wqhi + wbase;
    const __half* wl = g_wqlo + wbase;

    float acc[2][4][4];
#pragma unroll
    for (int i = 0; i < 2; i++)
#pragma unroll
        for (int j = 0; j < 4; j++)
#pragma unroll
            for (int e = 0; e < 4; e++) acc[i][j][e] = 0.f;

#define Q_ISSUE(cc) do { \
        int _k0 = (cc) * CK; \
        uint32_t _S = sb + ((cc) % 3) * Q_STG; \
        cp16(_S + 0*A_TB + adst[0], xh + asrc[0] + _k0); \
        cp16(_S + 0*A_TB + adst[1], xh + asrc[1] + _k0); \
        cp16(_S + A_TB + 0*B_TB + bdst, wh + bsrc + _k0); \
        cp16(_S + A_TB + 1*B_TB + bdst, wl + bsrc + _k0); \
        CP_COMMIT(); \
    } while (0)

    Q_ISSUE(0); Q_ISSUE(1); Q_ISSUE(2);

    // ---- inline ratio: overlaps the pipeline fill above ----
    // thread t: chunk = t>>6 (16 groups), dd = t&63 -> partial sums to smem
    {
        float* rp = (float*)(smem + Q_RP);       // [2][4][64]
        float* rs = (float*)(smem + Q_RS);       // [64]
        int chunk = tid >> 6, dd = tid & 63;
        float s1 = 0.f, s2 = 0.f;
        int i0 = chunk * 16;
#pragma unroll 16
        for (int i = i0; i < i0 + 16; i++) {
            size_t o = ((size_t)b * GROUPS + i) * D_MODEL + d0 + dd;
            s1 += g_part1[o];
            s2 += g_part2[o];
        }
        rp[0 * 256 + chunk * 64 + dd] = s1;
        rp[1 * 256 + chunk * 64 + dd] = s2;
        __syncthreads();
        if (tid < 64) {
            float S1 = rp[0 * 256 + 0 * 64 + tid] + rp[0 * 256 + 1 * 64 + tid]
                     + rp[0 * 256 + 2 * 64 + tid] + rp[0 * 256 + 3 * 64 + tid];
            float S2 = rp[1 * 256 + 0 * 64 + tid] + rp[1 * 256 + 1 * 64 + tid]
                     + rp[1 * 256 + 2 * 64 + tid] + rp[1 * 256 + 3 * 64 + tid];
            rs[tid] = S1 / S2;
        }
        // no extra sync needed here: mainloop's first CP_WAIT2+__syncthreads
        // orders rs[] writes before any epilogue read
    }

    for (int c = 0; c < NIT; c++) {
        CP_WAIT2();
        __syncthreads();
        const uint32_t sAh = sb + (c % 3) * Q_STG;
        const uint32_t sBh = sAh + A_TB;
        const uint32_t sBl = sBh + B_TB;
#pragma unroll
        for (int ks = 0; ks < 2; ks++) {
            uint32_t ah[2][4], bh[2][4], bl[2][4];
            ldsm4(ah[0], sAh + offA[0][ks]);
            ldsm4(ah[1], sAh + offA[1][ks]);
            ldsm4(bh[0], sBh + offB[0][ks]);
            ldsm4(bh[1], sBh + offB[1][ks]);
            ldsm4(bl[0], sBl + offB[0][ks]);
            ldsm4(bl[1], sBl + offB[1][ks]);
#pragma unroll
            for (int i = 0; i < 2; i++)
#pragma unroll
                for (int j = 0; j < 4; j++) {
                    mma16816(acc[i][j], ah[i], &bh[j >> 1][(j & 1) * 2]);
                    mma16816(acc[i][j], ah[i], &bl[j >> 1][(j & 1) * 2]);
                }
        }
        __syncthreads();
        if (c + 3 < NIT) Q_ISSUE(c + 3);
    }
#undef Q_ISSUE

    // ---- epilogue: sigmoid * ratio (from smem) via transpose, coalesced out ----
    const int colb = wn * 32 + (L & 3) * 2;
    const float* rs = (const float*)(smem + Q_RS);
    float2 bq2[4], rt2[4];
#pragma unroll
    for (int j = 0; j < 4; j++) {
        bq2[j] = *(const float2*)(bq + d0 + colb + j * 8);
        rt2[j] = *(const float2*)(rs + colb + j * 8);
    }
    float* tb = (float*)smem;
    __syncthreads();   // all reads of rs done? rt2 loaded above; protect tb overwrite of stages
#pragma unroll
    for (int i = 0; i < 2; i++)
#pragma unroll
        for (int h = 0; h < 2; h++) {
            int row = wm * 32 + i * 16 + (L >> 2) + h * 8;
#pragma unroll
            for (int j = 0; j < 4; j++) {
                float q0 = acc[i][j][h * 2 + 0] + bq2[j].x;
                float q1 = acc[i][j][h * 2 + 1] + bq2[j].y;
                float v0 = rt2[j].x / (1.f + __expf(-q0));
                float v1 = rt2[j].y / (1.f + __expf(-q1));
                tb[row * TPITCH + colb + j * 8 + 0] = v0;
                tb[row * TPITCH + colb + j * 8 + 1] = v1;
            }
        }
    __syncthreads();
    float* outp = out + ((size_t)b * SEQ + s0) * D_MODEL + d0;
#pragma unroll
    for (int i = 0; i < 8; i++) {
        int idx = tid + i * THREADS;
        int r = idx >> 4, c4 = idx & 15;
        float4 v = *(float4*)(tb + r * TPITCH + c4 * 4);
        *(float4*)(outp + (size_t)r * D_MODEL + c4 * 4) = v;
    }
}

// ---------------------------------------------------------------------------
extern "C" void kernel_launch(void* const* d_in, const int* in_sizes, int n_in,
                              void* d_out, int out_size)
{
    const float* X1 = (const float*)d_in[0];
    const float* X2 = (const float*)d_in[1];
    const float* Wq = (const float*)d_in[2];
    const float* bq = (const float*)d_in[3];
    const float* Wk = (const float*)d_in[4];
    const float* bk = (const float*)d_in[5];
    const float* Wv = (const float*)d_in[6];
    const float* bv = (const float*)d_in[7];
    const float* PB = (const float*)d_in[8];
    float* out = (float*)d_out;

    cudaFuncSetAttribute(kv_kernel, cudaFuncAttributeMaxDynamicSharedMemorySize, KV_SMEM);
    cudaFuncSetAttribute(q_kernel,  cudaFuncAttributeMaxDynamicSharedMemorySize, Q_SMEM);

    const int xn4 = XELEMS / 4, wn4 = WELEMS / 4;
    dim3 gx((xn4 + 255) / 256, 1, 2);
    dim3 gw((wn4 + 255) / 256, 1, 3);
    split_x_kernel<<<gx, 256>>>((const float4*)X1, (const float4*)X2);
    split_w_kernel<<<gw, 256>>>((const float4*)Wq, (const float4*)Wk, (const float4*)Wv);

    dim3 grid(DT, ST, BATCH);
    kv_kernel<<<grid, THREADS, KV_SMEM>>>(bk, bv, PB);
    q_kernel<<<grid, THREADS, Q_SMEM>>>(bq, out);
}

// round 17
// speedup vs baseline: 1.7087x; 1.4094x over previous
#include <cuda_runtime.h>
#include <cuda_fp16.h>
#include <cstdint>
#include <math.h>

#define D_MODEL 512
#define SEQ     2048
#define BATCH   8

#define TILE_M  128
#define TILE_N  64
#define CK      32                   // k elems per chunk
#define NIT     (D_MODEL / CK)       // 16 mainloop iterations
#define THREADS 256
#define DT      (D_MODEL / TILE_N)   // 8
#define ST      (SEQ / TILE_M)       // 16
#define GROUPS  (ST * 4)             // 64 partial rowgroups per (b,d)

// smem tiles: rows are 64B (32 halfs)
#define A_TB    (TILE_M * 64)        // 8192
#define B_TB    (TILE_N * 64)        // 4096
// kv stage: A = x1hi, x2hi ; B = wkhi, wvhi
#define KV_STG  (2*A_TB + 2*B_TB)    // 24576
#define KV_SMEM (3 * KV_STG)         // 73728 -> 2 CTA/SM
// q stage: A = x1hi ; B = wqhi ; + inline-ratio scratch
#define Q_STG   (A_TB + B_TB)        // 12288
#define Q_RP    (3 * Q_STG)          // rp[2][4][64] floats @ 36864
#define Q_RS    (Q_RP + 2048)        // ratio_s[64] floats  @ 38912
#define Q_SMEM  (Q_RS + 256)         // 39168 -> 2 CTA/SM
#define TPITCH  68

// ---------------- device scratch (allocation-free rule) ----------------
#define XELEMS (BATCH * SEQ * D_MODEL)
#define WELEMS (D_MODEL * D_MODEL)
__device__ __half g_x1hi[XELEMS];
__device__ __half g_x2hi[XELEMS];
__device__ __half g_wqhi[WELEMS];
__device__ __half g_wkhi[WELEMS];
__device__ __half g_wvhi[WELEMS];
__device__ float g_part1[BATCH * GROUPS * D_MODEL];
__device__ float g_part2[BATCH * GROUPS * D_MODEL];

// ---------------- PTX helpers ----------------
__device__ __forceinline__ uint32_t smem_u32(const void* p) {
    uint32_t a;
    asm("{ .reg .u64 t; cvta.to.shared.u64 t, %1; cvt.u32.u64 %0, t; }" : "=r"(a) : "l"(p));
    return a;
}
__device__ __forceinline__ void cp16(uint32_t dst, const void* src) {
    asm volatile("cp.async.cg.shared.global [%0], [%1], 16;" :: "r"(dst), "l"(src) : "memory");
}
#define CP_COMMIT() asm volatile("cp.async.commit_group;" ::: "memory")
#define CP_WAIT2()  asm volatile("cp.async.wait_group 2;" ::: "memory")

__device__ __forceinline__ void ldsm4(uint32_t* r, uint32_t addr) {
    asm volatile("ldmatrix.sync.aligned.m8n8.x4.shared.b16 {%0,%1,%2,%3}, [%4];"
        : "=r"(r[0]), "=r"(r[1]), "=r"(r[2]), "=r"(r[3]) : "r"(addr));
}
__device__ __forceinline__ void mma16816(float* c, const uint32_t* a, const uint32_t* b) {
    asm volatile("mma.sync.aligned.m16n8k16.row.col.f32.f16.f16.f32 "
        "{%0,%1,%2,%3}, {%4,%5,%6,%7}, {%8,%9}, {%0,%1,%2,%3};"
        : "+f"(c[0]), "+f"(c[1]), "+f"(c[2]), "+f"(c[3])
        : "r"(a[0]), "r"(a[1]), "r"(a[2]), "r"(a[3]), "r"(b[0]), "r"(b[1]));
}

// swizzled byte offset within a tile: row r (64B rows), 16B chunk c8 in 0..3
__device__ __forceinline__ uint32_t soff(int r, int c8) {
    return (uint32_t)(r * 64 + ((c8 ^ ((r >> 1) & 3)) * 16));
}

// ---------------------------------------------------------------------------
// split kernels: fp32 -> fp16 (hi only), layout preserved
// ---------------------------------------------------------------------------
__device__ __forceinline__ void cvt_store(const float4* src, uint2* hi, int i)
{
    float4 x = src[i];
    __half h0 = __float2half_rn(x.x), h1 = __float2half_rn(x.y);
    __half h2 = __float2half_rn(x.z), h3 = __float2half_rn(x.w);
    __half2 ha = __halves2half2(h0, h1), hb = __halves2half2(h2, h3);
    uint2 uh;
    uh.x = *(uint32_t*)&ha; uh.y = *(uint32_t*)&hb;
    hi[i] = uh;
}

__global__ void split_x_kernel(const float4* __restrict__ X1, const float4* __restrict__ X2)
{
    int i = blockIdx.x * blockDim.x + threadIdx.x;
    if (i >= XELEMS / 4) return;
    if (blockIdx.z == 0) cvt_store(X1, (uint2*)g_x1hi, i);
    else                 cvt_store(X2, (uint2*)g_x2hi, i);
}

__global__ void split_w_kernel(const float4* __restrict__ Wq,
                               const float4* __restrict__ Wk,
                               const float4* __restrict__ Wv)
{
    int i = blockIdx.x * blockDim.x + threadIdx.x;
    if (i >= WELEMS / 4) return;
    if (blockIdx.z == 0)      cvt_store(Wq, (uint2*)g_wqhi, i);
    else if (blockIdx.z == 1) cvt_store(Wk, (uint2*)g_wkhi, i);
    else                      cvt_store(Wv, (uint2*)g_wvhi, i);
}

// ---------------------------------------------------------------------------
// kv kernel: k = X1hi@Wkhi^T, v = X2hi@Wvhi^T (single fp16 term each),
// fused epilogue: partials of sum_s ws*e^(k+bk)*(v+bv) and sum_s ws*e^(k+bk)
// ---------------------------------------------------------------------------
__global__ __launch_bounds__(THREADS, 2) void kv_kernel(
    const float* __restrict__ bk, const float* __restrict__ bv,
    const float* __restrict__ PB)
{
    extern __shared__ __align__(128) char smem[];
    const uint32_t sb = smem_u32(smem);
    const int tid = threadIdx.x, wid = tid >> 5, L = tid & 31;
    const int wm = wid & 3, wn = wid >> 2;

    const int dt = blockIdx.x, st = blockIdx.y, b = blockIdx.z;
    const int s0 = st * TILE_M, d0 = dt * TILE_N;

    int asrc[2]; uint32_t adst[2];
#pragma unroll
    for (int p = 0; p < 2; p++) {
        int idx = tid + p * THREADS;
        int r = idx >> 2, c8 = idx & 3;
        asrc[p] = r * D_MODEL + c8 * 8; adst[p] = soff(r, c8);
    }
    const int brow = tid >> 2, bc8 = tid & 3;
    const int bsrc = brow * D_MODEL + bc8 * 8;
    const uint32_t bdst = soff(brow, bc8);

    uint32_t offA[2][2], offB[2][2];
#pragma unroll
    for (int i = 0; i < 2; i++)
#pragma unroll
        for (int ks = 0; ks < 2; ks++) {
            int r = wm * 32 + i * 16 + (L & 7) + ((L >> 3) & 1) * 8;
            int c8 = ks * 2 + (L >> 4);
            offA[i][ks] = soff(r, c8);
        }
#pragma unroll
    for (int jp = 0; jp < 2; jp++)
#pragma unroll
        for (int ks = 0; ks < 2; ks++) {
            int n = wn * 32 + (jp * 2 + (L >> 4)) * 8 + (L & 7);
            int c8 = ks * 2 + ((L >> 3) & 1);
            offB[jp][ks] = soff(n, c8);
        }

    const size_t xbase = ((size_t)b * SEQ + s0) * D_MODEL;
    const __half* x1h = g_x1hi + xbase;
    const __half* x2h = g_x2hi + xbase;
    const size_t wbase = (size_t)d0 * D_MODEL;
    const __half* wkh = g_wkhi + wbase;
    const __half* wvh = g_wvhi + wbase;

    float accK[2][4][4], accV[2][4][4];
#pragma unroll
    for (int i = 0; i < 2; i++)
#pragma unroll
        for (int j = 0; j < 4; j++)
#pragma unroll
            for (int e = 0; e < 4; e++) { accK[i][j][e] = 0.f; accV[i][j][e] = 0.f; }

#define KV_ISSUE(cc) do { \
        int _k0 = (cc) * CK; \
        uint32_t _S = sb + ((cc) % 3) * KV_STG; \
        cp16(_S + 0*A_TB + adst[0], x1h + asrc[0] + _k0); \
        cp16(_S + 0*A_TB + adst[1], x1h + asrc[1] + _k0); \
        cp16(_S + 1*A_TB + adst[0], x2h + asrc[0] + _k0); \
        cp16(_S + 1*A_TB + adst[1], x2h + asrc[1] + _k0); \
        cp16(_S + 2*A_TB + 0*B_TB + bdst, wkh + bsrc + _k0); \
        cp16(_S + 2*A_TB + 1*B_TB + bdst, wvh + bsrc + _k0); \
        CP_COMMIT(); \
    } while (0)

    KV_ISSUE(0); KV_ISSUE(1); KV_ISSUE(2);

    for (int c = 0; c < NIT; c++) {
        CP_WAIT2();
        __syncthreads();
        const uint32_t sA1h = sb + (c % 3) * KV_STG;
        const uint32_t sA2h = sA1h + A_TB;
        const uint32_t sBB  = sA1h + 2 * A_TB;
#pragma unroll
        for (int ks = 0; ks < 2; ks++) {
            uint32_t a1[2][4], a2[2][4], bk_[2][4], bv_[2][4];
            ldsm4(a1[0], sA1h + offA[0][ks]);
            ldsm4(a1[1], sA1h + offA[1][ks]);
            ldsm4(a2[0], sA2h + offA[0][ks]);
            ldsm4(a2[1], sA2h + offA[1][ks]);
            ldsm4(bk_[0], sBB + 0*B_TB + offB[0][ks]);
            ldsm4(bk_[1], sBB + 0*B_TB + offB[1][ks]);
            ldsm4(bv_[0], sBB + 1*B_TB + offB[0][ks]);
            ldsm4(bv_[1], sBB + 1*B_TB + offB[1][ks]);
#pragma unroll
            for (int i = 0; i < 2; i++)
#pragma unroll
                for (int j = 0; j < 4; j++) {
                    mma16816(accK[i][j], a1[i], &bk_[j >> 1][(j & 1) * 2]);
                    mma16816(accV[i][j], a2[i], &bv_[j >> 1][(j & 1) * 2]);
                }
        }
        __syncthreads();
        if (c + 3 < NIT) KV_ISSUE(c + 3);
    }
#undef KV_ISSUE

    // ---- epilogue (verified) ----
    float ws[2][2];
#pragma unroll
    for (int i = 0; i < 2; i++)
#pragma unroll
        for (int h = 0; h < 2; h++)
            ws[i][h] = __expf(PB[s0 + wm * 32 + i * 16 + (L >> 2) + h * 8]);

    const int colb = d0 + wn * 32 + (L & 3) * 2;
    float2 bk2[4], bv2[4];
#pragma unroll
    for (int j = 0; j < 4; j++) {
        bk2[j] = *(const float2*)(bk + colb + j * 8);
        bv2[j] = *(const float2*)(bv + colb + j * 8);
    }
    float p1[8], p2[8];
#pragma unroll
    for (int u = 0; u < 8; u++) { p1[u] = 0.f; p2[u] = 0.f; }
#pragma unroll
    for (int i = 0; i < 2; i++)
#pragma unroll
        for (int h = 0; h < 2; h++)
#pragma unroll
            for (int j = 0; j < 4; j++) {
                float ek0 = ws[i][h] * __expf(accK[i][j][h * 2 + 0] + bk2[j].x);
                float ek1 = ws[i][h] * __expf(accK[i][j][h * 2 + 1] + bk2[j].y);
                p2[j * 2 + 0] += ek0;
                p2[j * 2 + 1] += ek1;
                p1[j * 2 + 0] += ek0 * (accV[i][j][h * 2 + 0] + bv2[j].x);
                p1[j * 2 + 1] += ek1 * (accV[i][j][h * 2 + 1] + bv2[j].y);
            }
#pragma unroll
    for (int sft = 4; sft <= 16; sft <<= 1)
#pragma unroll
        for (int u = 0; u < 8; u++) {
            p1[u] += __shfl_xor_sync(0xffffffffu, p1[u], sft);
            p2[u] += __shfl_xor_sync(0xffffffffu, p2[u], sft);
        }
    if ((L >> 2) == 0) {
        size_t pb = (((size_t)b * ST + st) * 4 + wm) * D_MODEL + colb;
#pragma unroll
        for (int j = 0; j < 4; j++) {
            *(float2*)(g_part1 + pb + j * 8) = make_float2(p1[j * 2], p1[j * 2 + 1]);
            *(float2*)(g_part2 + pb + j * 8) = make_float2(p2[j * 2], p2[j * 2 + 1]);
        }
    }
}

// ---------------------------------------------------------------------------
// q kernel: inline ratio reduction (overlapped with pipeline fill) +
// q = X1hi@Wqhi^T + bq (single term), out = sigmoid(q) * ratio
// ---------------------------------------------------------------------------
__global__ __launch_bounds__(THREADS, 2) void q_kernel(
    const float* __restrict__ bq, float* __restrict__ out)
{
    extern __shared__ __align__(128) char smem[];
    const uint32_t sb = smem_u32(smem);
    const int tid = threadIdx.x, wid = tid >> 5, L = tid & 31;
    const int wm = wid & 3, wn = wid >> 2;

    const int dt = blockIdx.x, st = blockIdx.y, b = blockIdx.z;
    const int s0 = st * TILE_M, d0 = dt * TILE_N;

    int asrc[2]; uint32_t adst[2];
#pragma unroll
    for (int p = 0; p < 2; p++) {
        int idx = tid + p * THREADS;
        int r = idx >> 2, c8 = idx & 3;
        asrc[p] = r * D_MODEL + c8 * 8; adst[p] = soff(r, c8);
    }
    const int brow = tid >> 2, bc8 = tid & 3;
    const int bsrc = brow * D_MODEL + bc8 * 8;
    const uint32_t bdst = soff(brow, bc8);

    uint32_t offA[2][2], offB[2][2];
#pragma unroll
    for (int i = 0; i < 2; i++)
#pragma unroll
        for (int ks = 0; ks < 2; ks++) {
            int r = wm * 32 + i * 16 + (L & 7) + ((L >> 3) & 1) * 8;
            int c8 = ks * 2 + (L >> 4);
            offA[i][ks] = soff(r, c8);
        }
#pragma unroll
    for (int jp = 0; jp < 2; jp++)
#pragma unroll
        for (int ks = 0; ks < 2; ks++) {
            int n = wn * 32 + (jp * 2 + (L >> 4)) * 8 + (L & 7);
            int c8 = ks * 2 + ((L >> 3) & 1);
            offB[jp][ks] = soff(n, c8);
        }

    const size_t xbase = ((size_t)b * SEQ + s0) * D_MODEL;
    const __half* xh = g_x1hi + xbase;
    const __half* wh = g_wqhi + (size_t)d0 * D_MODEL;

    float acc[2][4][4];
#pragma unroll
    for (int i = 0; i < 2; i++)
#pragma unroll
        for (int j = 0; j < 4; j++)
#pragma unroll
            for (int e = 0; e < 4; e++) acc[i][j][e] = 0.f;

#define Q_ISSUE(cc) do { \
        int _k0 = (cc) * CK; \
        uint32_t _S = sb + ((cc) % 3) * Q_STG; \
        cp16(_S + 0*A_TB + adst[0], xh + asrc[0] + _k0); \
        cp16(_S + 0*A_TB + adst[1], xh + asrc[1] + _k0); \
        cp16(_S + A_TB + bdst, wh + bsrc + _k0); \
        CP_COMMIT(); \
    } while (0)

    Q_ISSUE(0); Q_ISSUE(1); Q_ISSUE(2);

    // ---- inline ratio: overlaps the pipeline fill above ----
    {
        float* rp = (float*)(smem + Q_RP);       // [2][4][64]
        float* rs = (float*)(smem + Q_RS);       // [64]
        int chunk = tid >> 6, dd = tid & 63;
        float s1 = 0.f, s2 = 0.f;
        int i0 = chunk * 16;
#pragma unroll 16
        for (int i = i0; i < i0 + 16; i++) {
            size_t o = ((size_t)b * GROUPS + i) * D_MODEL + d0 + dd;
            s1 += g_part1[o];
            s2 += g_part2[o];
        }
        rp[0 * 256 + chunk * 64 + dd] = s1;
        rp[1 * 256 + chunk * 64 + dd] = s2;
        __syncthreads();
        if (tid < 64) {
            float S1 = rp[0 * 256 + 0 * 64 + tid] + rp[0 * 256 + 1 * 64 + tid]
                     + rp[0 * 256 + 2 * 64 + tid] + rp[0 * 256 + 3 * 64 + tid];
            float S2 = rp[1 * 256 + 0 * 64 + tid] + rp[1 * 256 + 1 * 64 + tid]
                     + rp[1 * 256 + 2 * 64 + tid] + rp[1 * 256 + 3 * 64 + tid];
            rs[tid] = S1 / S2;
        }
        // mainloop's first CP_WAIT2+__syncthreads orders rs[] before epilogue reads
    }

    for (int c = 0; c < NIT; c++) {
        CP_WAIT2();
        __syncthreads();
        const uint32_t sAh = sb + (c % 3) * Q_STG;
        const uint32_t sBh = sAh + A_TB;
#pragma unroll
        for (int ks = 0; ks < 2; ks++) {
            uint32_t ah[2][4], bh[2][4];
            ldsm4(ah[0], sAh + offA[0][ks]);
            ldsm4(ah[1], sAh + offA[1][ks]);
            ldsm4(bh[0], sBh + offB[0][ks]);
            ldsm4(bh[1], sBh + offB[1][ks]);
#pragma unroll
            for (int i = 0; i < 2; i++)
#pragma unroll
                for (int j = 0; j < 4; j++)
                    mma16816(acc[i][j], ah[i], &bh[j >> 1][(j & 1) * 2]);
        }
        __syncthreads();
        if (c + 3 < NIT) Q_ISSUE(c + 3);
    }
#undef Q_ISSUE

    // ---- epilogue: sigmoid * ratio (from smem) via transpose, coalesced out ----
    const int colb = wn * 32 + (L & 3) * 2;
    const float* rs = (const float*)(smem + Q_RS);
    float2 bq2[4], rt2[4];
#pragma unroll
    for (int j = 0; j < 4; j++) {
        bq2[j] = *(const float2*)(bq + d0 + colb + j * 8);
        rt2[j] = *(const float2*)(rs + colb + j * 8);
    }
    float* tb = (float*)smem;
    __syncthreads();
#pragma unroll
    for (int i = 0; i < 2; i++)
#pragma unroll
        for (int h = 0; h < 2; h++) {
            int row = wm * 32 + i * 16 + (L >> 2) + h * 8;
#pragma unroll
            for (int j = 0; j < 4; j++) {
                float q0 = acc[i][j][h * 2 + 0] + bq2[j].x;
                float q1 = acc[i][j][h * 2 + 1] + bq2[j].y;
                float v0 = rt2[j].x / (1.f + __expf(-q0));
                float v1 = rt2[j].y / (1.f + __expf(-q1));
                tb[row * TPITCH + colb + j * 8 + 0] = v0;
                tb[row * TPITCH + colb + j * 8 + 1] = v1;
            }
        }
    __syncthreads();
    float* outp = out + ((size_t)b * SEQ + s0) * D_MODEL + d0;
#pragma unroll
    for (int i = 0; i < 8; i++) {
        int idx = tid + i * THREADS;
        int r = idx >> 4, c4 = idx & 15;
        float4 v = *(float4*)(tb + r * TPITCH + c4 * 4);
        *(float4*)(outp + (size_t)r * D_MODEL + c4 * 4) = v;
    }
}

// ---------------------------------------------------------------------------
extern "C" void kernel_launch(void* const* d_in, const int* in_sizes, int n_in,
                              void* d_out, int out_size)
{
    const float* X1 = (const float*)d_in[0];
    const float* X2 = (const float*)d_in[1];
    const float* Wq = (const float*)d_in[2];
    const float* bq = (const float*)d_in[3];
    const float* Wk = (const float*)d_in[4];
    const float* bk = (const float*)d_in[5];
    const float* Wv = (const float*)d_in[6];
    const float* bv = (const float*)d_in[7];
    const float* PB = (const float*)d_in[8];
    float* out = (float*)d_out;

    cudaFuncSetAttribute(kv_kernel, cudaFuncAttributeMaxDynamicSharedMemorySize, KV_SMEM);
    cudaFuncSetAttribute(q_kernel,  cudaFuncAttributeMaxDynamicSharedMemorySize, Q_SMEM);

    const int xn4 = XELEMS / 4, wn4 = WELEMS / 4;
    dim3 gx((xn4 + 255) / 256, 1, 2);
    dim3 gw((wn4 + 255) / 256, 1, 3);
    split_x_kernel<<<gx, 256>>>((const float4*)X1, (const float4*)X2);
    split_w_kernel<<<gw, 256>>>((const float4*)Wq, (const float4*)Wk, (const float4*)Wv);

    dim3 grid(DT, ST, BATCH);
    kv_kernel<<<grid, THREADS, KV_SMEM>>>(bk, bv, PB);
    q_kernel<<<grid, THREADS, Q_SMEM>>>(bq, out);
}